// round 1
// baseline (speedup 1.0000x reference)
#include <cuda_runtime.h>

#define BB 32
#define TT 512
#define DD 384
#define ML 4096
#define D4 (DD / 4)   // 96 float4 per row

// Scratch: token index per (batch, frame); -1 => invalid (beyond total)
__device__ int g_tokmap[BB * ML];

// Kernel A: per-batch inclusive scan of durations, scatter token ids into
// g_tokmap, write mel_pos (as float) directly into output tail.
__global__ void lr_scan_scatter(const int* __restrict__ dur,
                                float* __restrict__ mel_pos_out) {
    __shared__ int s[TT];
    __shared__ int s_total;
    const int b = blockIdx.x;
    const int t = threadIdx.x;

    const int d = dur[b * TT + t];
    s[t] = d;
    __syncthreads();

    // Kogge-Stone inclusive scan over 512 elements
    #pragma unroll
    for (int off = 1; off < TT; off <<= 1) {
        int v = (t >= off) ? s[t - off] : 0;
        __syncthreads();
        s[t] += v;
        __syncthreads();
    }
    const int cum = s[t];
    if (t == TT - 1) s_total = cum;
    __syncthreads();
    const int total = s_total;

    // Fill invalid entries + mel_pos. Valid tokmap entries are fully covered
    // by the scatter below (union of [cum-d, cum) over t == [0, total)).
    for (int f = t; f < ML; f += TT) {
        const bool valid = f < total;
        if (!valid) g_tokmap[b * ML + f] = -1;
        mel_pos_out[b * ML + f] = valid ? (float)(f + 1) : 0.0f;
    }

    // Scatter: token t owns frames [cum-d, cum). d < 8 so at most 7 writes.
    const int start = cum - d;
    for (int f = start; f < cum; ++f) {
        g_tokmap[b * ML + f] = t;
    }
}

// Kernel B: coalesced float4 gather. One float4 per thread.
__global__ void lr_gather(const float4* __restrict__ x,
                          float4* __restrict__ out) {
    const int idx = blockIdx.x * blockDim.x + threadIdx.x;
    const int N4 = BB * ML * D4;
    if (idx >= N4) return;

    const int c4 = idx % D4;
    const int bf = idx / D4;       // b * ML + f
    const int b  = bf / ML;

    const int tok = __ldg(&g_tokmap[bf]);
    float4 v;
    if (tok >= 0) {
        v = __ldg(&x[(b * TT + tok) * D4 + c4]);
    } else {
        v = make_float4(0.0f, 0.0f, 0.0f, 0.0f);
    }
    out[idx] = v;
}

extern "C" void kernel_launch(void* const* d_in, const int* in_sizes, int n_in,
                              void* d_out, int out_size) {
    const float* x   = (const float*)d_in[0];
    const int*   dur = (const int*)d_in[1];
    // d_in[2] = max_length scalar (compile-time constant 4096 here)

    float* out = (float*)d_out;                 // [B, ML, D] f32
    float* mel = out + (size_t)BB * ML * DD;    // [B, ML] written as float

    lr_scan_scatter<<<BB, TT>>>(dur, mel);

    const int N4 = BB * ML * D4;
    lr_gather<<<(N4 + 255) / 256, 256>>>((const float4*)x, (float4*)out);
}

// round 2
// speedup vs baseline: 1.8517x; 1.8517x over previous
#include <cuda_runtime.h>

#define BB 32
#define TT 512
#define DD 384
#define ML 4096
#define D4 (DD / 4)   // 96 float4 per row

// Scratch: token index per (batch, frame); -1 => invalid (beyond total)
__device__ int g_tokmap[BB * ML];

// Kernel A: per-batch inclusive scan of durations, scatter token ids into
// g_tokmap, write mel_pos (as float) directly into output tail.
__global__ void lr_scan_scatter(const int* __restrict__ dur,
                                float* __restrict__ mel_pos_out) {
    __shared__ int s[TT];
    __shared__ int s_total;
    const int b = blockIdx.x;
    const int t = threadIdx.x;

    const int d = dur[b * TT + t];
    s[t] = d;
    __syncthreads();

    // Kogge-Stone inclusive scan over 512 elements
    #pragma unroll
    for (int off = 1; off < TT; off <<= 1) {
        int v = (t >= off) ? s[t - off] : 0;
        __syncthreads();
        s[t] += v;
        __syncthreads();
    }
    const int cum = s[t];
    if (t == TT - 1) s_total = cum;
    __syncthreads();
    const int total = s_total;

    // Fill invalid entries + mel_pos. Valid tokmap entries are fully covered
    // by the scatter below.
    for (int f = t; f < ML; f += TT) {
        const bool valid = f < total;
        if (!valid) g_tokmap[b * ML + f] = -1;
        mel_pos_out[b * ML + f] = valid ? (float)(f + 1) : 0.0f;
    }

    // Scatter: token t owns frames [cum-d, cum). d < 8 so at most 7 writes.
    const int start = cum - d;
    for (int f = start; f < cum; ++f) {
        g_tokmap[b * ML + f] = t;
    }
}

// Kernel B: one 96-thread block per 4-frame group. threadIdx.x == c4.
// int4 tokmap load (broadcast), 4 independent x gathers (MLP=4),
// 4 streaming stores.
__global__ __launch_bounds__(96) void lr_gather(const float4* __restrict__ x,
                                                float4* __restrict__ out) {
    const int c4 = threadIdx.x;          // 0..95
    const int fq = blockIdx.x;           // 0..BB*ML/4-1
    const int b  = fq >> 10;             // ML/4 = 1024 groups per batch
    const int f0 = (fq & 1023) << 2;

    const int4 toks = *reinterpret_cast<const int4*>(&g_tokmap[b * ML + f0]);

    const float4* xb = x + (size_t)b * TT * D4;
    const float4 z = make_float4(0.0f, 0.0f, 0.0f, 0.0f);

    float4 v0 = (toks.x >= 0) ? __ldg(&xb[toks.x * D4 + c4]) : z;
    float4 v1 = (toks.y >= 0) ? __ldg(&xb[toks.y * D4 + c4]) : z;
    float4 v2 = (toks.z >= 0) ? __ldg(&xb[toks.z * D4 + c4]) : z;
    float4 v3 = (toks.w >= 0) ? __ldg(&xb[toks.w * D4 + c4]) : z;

    float4* o = out + (size_t)(b * ML + f0) * D4 + c4;
    __stcs(o,          v0);
    __stcs(o + D4,     v1);
    __stcs(o + 2 * D4, v2);
    __stcs(o + 3 * D4, v3);
}

extern "C" void kernel_launch(void* const* d_in, const int* in_sizes, int n_in,
                              void* d_out, int out_size) {
    const float* x   = (const float*)d_in[0];
    const int*   dur = (const int*)d_in[1];

    float* out = (float*)d_out;                 // [B, ML, D] f32
    float* mel = out + (size_t)BB * ML * DD;    // [B, ML] written as float

    lr_scan_scatter<<<BB, TT>>>(dur, mel);

    lr_gather<<<BB * (ML / 4), 96>>>((const float4*)x, (float4*)out);
}